// round 15
// baseline (speedup 1.0000x reference)
#include <cuda_runtime.h>
#include <cuda_bf16.h>
#include <cuda_fp16.h>
#include <math.h>

#define MAXN 50048           // divisible by 16
#define BCAP 128             // bucket capacity per node (in-degree ~Poisson(32), max ~58)
#define MAXE 1600000

// ---------------- per-slice device scratch (static; no allocations) ----------------
__device__ __align__(16) float  g_dinv[2][MAXN];
__device__ __align__(16) int    g_cnt[2][MAXN];
__device__ __align__(16) int    g_bkt[2][(size_t)MAXN * BCAP];
__device__ __align__(16) __half g_m[2][(size_t)MAXN * 128];     // L0: unscaled; L1: dinv-prescaled
__device__ __align__(16) float  g_agg0[2][(size_t)MAXN * 64];
__device__ __align__(16) float  g_agg1[2][(size_t)MAXN * 128];
__device__ __align__(16) float  g_proj[2][(size_t)MAXN * 128];
// per slice: [0,128) stats layer0 (sum,sq F=64); [128,384) layer1 (F=128)
__device__ __align__(16) float  g_stats[2][392];

// ---------------- static streams / events (host-side, created at load) ----------------
static cudaStream_t g_str[4];
static cudaEvent_t  g_ev[10];
static int g_init_streams = []() {
    for (int i = 0; i < 4; i++) cudaStreamCreateWithFlags(&g_str[i], cudaStreamNonBlocking);
    for (int i = 0; i < 10; i++) cudaEventCreateWithFlags(&g_ev[i], cudaEventDisableTiming);
    return 0;
}();

// nan_to_num(nan=0, posinf=100, neginf=-100)
__device__ __forceinline__ float san(float v) {
    if (isnan(v)) return 0.f;
    if (isinf(v)) return v > 0.f ? 100.f : -100.f;
    return v;
}

__device__ __forceinline__ unsigned h2u(__half2 h) { return *(unsigned*)&h; }

__device__ __forceinline__ float4 ldh4(const __half* p) {
    uint2 w = *(const uint2*)p;
    float2 a = __half22float2(*(__half2*)&w.x);
    float2 b = __half22float2(*(__half2*)&w.y);
    return make_float4(a.x, a.y, b.x, b.y);
}
__device__ __forceinline__ float2 ldh2(const __half* p) {
    return __half22float2(*(const __half2*)p);
}

// m16n8k16 f16xf16 -> f32 accumulate
__device__ __forceinline__ void mma16816(float* c, const unsigned* a, unsigned b0, unsigned b1) {
    asm volatile(
        "mma.sync.aligned.m16n8k16.row.col.f32.f16.f16.f32 "
        "{%0,%1,%2,%3}, {%4,%5,%6,%7}, {%8,%9}, {%0,%1,%2,%3};"
        : "+f"(c[0]), "+f"(c[1]), "+f"(c[2]), "+f"(c[3])
        : "r"(a[0]), "r"(a[1]), "r"(a[2]), "r"(a[3]), "r"(b0), "r"(b1));
}

// ---------------- single-pass bucketed CSR fill ----------------
__global__ void fill_kernel(const int* __restrict__ ei, int* __restrict__ cnt,
                            int* __restrict__ bkt, int E) {
    int e = blockIdx.x * blockDim.x + threadIdx.x;
    if (e < E) {
        int c = ei[E + e];
        int pos = atomicAdd(&cnt[c], 1);
        bkt[(unsigned)c * BCAP + pos] = ei[e];
    }
}

// dinv[i] = rsqrt(cnt[i]); block 0 also zeroes ALL 392 BN-stats words (strided)
__global__ void dinv_kernel(const int* __restrict__ cnt, float* __restrict__ dinv,
                            float* __restrict__ stats, int n) {
    int i = blockIdx.x * blockDim.x + threadIdx.x;
    if (blockIdx.x == 0) {
        for (int j = threadIdx.x; j < 392; j += 256) stats[j] = 0.f;
    }
    if (i < n) {
        int d = cnt[i];
        dinv[i] = d > 0 ? rsqrtf((float)d) : 0.f;
    }
}

// ================= HMMA GEMM (layer 0): C[128,64] = A[*,64] @ B[64,64], fp16 out ======
__global__ __launch_bounds__(256) void hgemm0_kernel(const float* __restrict__ A,
                                                     const float* __restrict__ B,
                                                     __half* __restrict__ C, int n) {
    constexpr int ASTR = 72;
    constexpr int BSTR = 72;
    __shared__ __half  As[128 * ASTR];
    __shared__ unsigned Bs[32 * BSTR];

    int tid = threadIdx.x;
    int row0 = blockIdx.x * 128;

    #pragma unroll
    for (int i = 0; i < 16; i++) {
        int idx = tid + 256 * i;
        int r = idx >> 5, kp = idx & 31;
        float v0 = 0.f, v1 = 0.f;
        if (row0 + r < n) {
            unsigned o = (unsigned)(row0 + r) * 64u + kp * 2;
            float2 av = *(const float2*)&A[o];
            v0 = av.x; v1 = av.y;
        }
        *(unsigned*)&As[r * ASTR + kp * 2] = h2u(__floats2half2_rn(v0, v1));
    }
    #pragma unroll
    for (int i = 0; i < 8; i++) {
        int idx = tid + 256 * i;
        int kp = idx >> 6, nn = idx & 63;
        Bs[kp * BSTR + nn] = h2u(__floats2half2_rn(B[(2 * kp) * 64 + nn],
                                                   B[(2 * kp + 1) * 64 + nn]));
    }
    __syncthreads();

    int warp = tid >> 5, lane = tid & 31;
    int wr = warp >> 1, wc = warp & 1;
    int rbase = wr * 32, nbase = wc * 32;
    int g = lane >> 2, q = lane & 3;

    float acc[2][4][4];
    #pragma unroll
    for (int mt = 0; mt < 2; mt++)
        #pragma unroll
        for (int nt = 0; nt < 4; nt++)
            #pragma unroll
            for (int e = 0; e < 4; e++) acc[mt][nt][e] = 0.f;

    #pragma unroll
    for (int kk = 0; kk < 4; kk++) {
        unsigned a[2][4];
        #pragma unroll
        for (int mt = 0; mt < 2; mt++) {
            const __half* ap = &As[(rbase + mt * 16 + g) * ASTR + kk * 16 + q * 2];
            a[mt][0] = *(const unsigned*)ap;
            a[mt][1] = *(const unsigned*)(ap + 8 * ASTR);
            a[mt][2] = *(const unsigned*)(ap + 8);
            a[mt][3] = *(const unsigned*)(ap + 8 * ASTR + 8);
        }
        int kp = kk * 8 + q;
        #pragma unroll
        for (int nt = 0; nt < 4; nt++) {
            int nn = nbase + nt * 8 + g;
            unsigned b0 = Bs[kp * BSTR + nn];
            unsigned b1 = Bs[(kp + 4) * BSTR + nn];
            mma16816(acc[0][nt], a[0], b0, b1);
            mma16816(acc[1][nt], a[1], b0, b1);
        }
    }

    #pragma unroll
    for (int mt = 0; mt < 2; mt++) {
        #pragma unroll
        for (int h = 0; h < 2; h++) {
            int r = row0 + rbase + mt * 16 + g + h * 8;
            if (r < n) {
                #pragma unroll
                for (int nt = 0; nt < 4; nt++) {
                    float c0 = acc[mt][nt][h * 2], c1 = acc[mt][nt][h * 2 + 1];
                    int col = nbase + nt * 8 + q * 2;
                    *(unsigned*)&C[(unsigned)r * 64 + col] = h2u(__floats2half2_rn(c0, c1));
                }
            }
        }
    }
}

// ====== merged layer-1 GEMM: one A pass -> m1 (fp16*dinv) + proj (fp32); inline BN0 ======
__global__ __launch_bounds__(256) void hgemm1m_kernel(const float* __restrict__ agg0,
                                                      const float* __restrict__ x,
                                                      const float* __restrict__ stats,
                                                      const float* __restrict__ gam,
                                                      const float* __restrict__ bet,
                                                      const float* __restrict__ W1,
                                                      const float* __restrict__ R1,
                                                      const float* __restrict__ dinv,
                                                      __half* __restrict__ mOut,
                                                      float* __restrict__ projOut, int n) {
    constexpr int ASTR = 72;
    constexpr int BSTR = 264;
    __shared__ __half  As[64 * ASTR];
    __shared__ unsigned Bs[32 * BSTR];
    __shared__ float sab[128];

    int tid = threadIdx.x;
    int row0 = blockIdx.x * 64;

    if (tid < 64) {
        int c = tid;
        float inv_n = 1.f / (float)n;
        float mu = stats[c] * inv_n;
        float var = fmaxf(stats[64 + c] * inv_n - mu * mu, 0.f);
        float a = gam[c] * rsqrtf(var + 1e-5f);
        sab[c] = a;
        sab[64 + c] = bet[c] - a * mu;
    }
    __syncthreads();

    #pragma unroll
    for (int i = 0; i < 8; i++) {
        int idx = tid + 256 * i;
        int r = idx >> 5, kp = idx & 31;
        float v0 = 0.f, v1 = 0.f;
        if (row0 + r < n) {
            unsigned o = (unsigned)(row0 + r) * 64u + kp * 2;
            float2 av = *(const float2*)&agg0[o];
            float2 xv = *(const float2*)&x[o];
            float t0 = fmaf(sab[kp * 2], av.x, sab[64 + kp * 2]);
            float t1 = fmaf(sab[kp * 2 + 1], av.y, sab[64 + kp * 2 + 1]);
            v0 = san(fmaxf(t0, 0.f) + xv.x);
            v1 = san(fmaxf(t1, 0.f) + xv.y);
        }
        *(unsigned*)&As[r * ASTR + kp * 2] = h2u(__floats2half2_rn(v0, v1));
    }
    #pragma unroll
    for (int i = 0; i < 32; i++) {
        int idx = tid + 256 * i;
        int kp = idx >> 8, nn = idx & 255;
        float b0, b1;
        if (nn < 128) {
            b0 = W1[(2 * kp) * 128 + nn];
            b1 = W1[(2 * kp + 1) * 128 + nn];
        } else {
            b0 = R1[(2 * kp) * 128 + nn - 128];
            b1 = R1[(2 * kp + 1) * 128 + nn - 128];
        }
        Bs[kp * BSTR + nn] = h2u(__floats2half2_rn(b0, b1));
    }
    __syncthreads();

    int warp = tid >> 5, lane = tid & 31;
    int wr = warp >> 2, wc = warp & 3;
    int rbase = wr * 32, nbase = wc * 64;
    int g = lane >> 2, q = lane & 3;

    float acc[2][8][4];
    #pragma unroll
    for (int mt = 0; mt < 2; mt++)
        #pragma unroll
        for (int nt = 0; nt < 8; nt++)
            #pragma unroll
            for (int e = 0; e < 4; e++) acc[mt][nt][e] = 0.f;

    #pragma unroll
    for (int kk = 0; kk < 4; kk++) {
        unsigned a[2][4];
        #pragma unroll
        for (int mt = 0; mt < 2; mt++) {
            const __half* ap = &As[(rbase + mt * 16 + g) * ASTR + kk * 16 + q * 2];
            a[mt][0] = *(const unsigned*)ap;
            a[mt][1] = *(const unsigned*)(ap + 8 * ASTR);
            a[mt][2] = *(const unsigned*)(ap + 8);
            a[mt][3] = *(const unsigned*)(ap + 8 * ASTR + 8);
        }
        int kp = kk * 8 + q;
        #pragma unroll
        for (int nt = 0; nt < 8; nt++) {
            int nn = nbase + nt * 8 + g;
            unsigned b0 = Bs[kp * BSTR + nn];
            unsigned b1 = Bs[(kp + 4) * BSTR + nn];
            mma16816(acc[0][nt], a[0], b0, b1);
            mma16816(acc[1][nt], a[1], b0, b1);
        }
    }

    bool isM = (nbase < 128);
    #pragma unroll
    for (int mt = 0; mt < 2; mt++) {
        #pragma unroll
        for (int h = 0; h < 2; h++) {
            int r = row0 + rbase + mt * 16 + g + h * 8;
            if (r < n) {
                if (isM) {
                    float sc = dinv[r];
                    #pragma unroll
                    for (int nt = 0; nt < 8; nt++) {
                        float c0 = acc[mt][nt][h * 2] * sc, c1 = acc[mt][nt][h * 2 + 1] * sc;
                        int col = nbase + nt * 8 + q * 2;
                        *(unsigned*)&mOut[(unsigned)r * 128 + col] = h2u(__floats2half2_rn(c0, c1));
                    }
                } else {
                    #pragma unroll
                    for (int nt = 0; nt < 8; nt++) {
                        float c0 = acc[mt][nt][h * 2], c1 = acc[mt][nt][h * 2 + 1];
                        int col = nbase + nt * 8 + q * 2 - 128;
                        *(float2*)&projOut[(unsigned)r * 128 + col] = make_float2(c0, c1);
                    }
                }
            }
        }
    }
}

// ===== gather layer 0 (R13 form, 16-deep load pipeline): per-edge dinv + fused BN stats =====
__global__ __launch_bounds__(256) void gather64_kernel(const int* __restrict__ cnt,
                                                       const int* __restrict__ bkt,
                                                       const float* __restrict__ dinv,
                                                       const __half* __restrict__ m,
                                                       float* __restrict__ agg,
                                                       float* __restrict__ stats, int n) {
    __shared__ float ssum[64], ssq[64];
    if (threadIdx.x < 64) { ssum[threadIdx.x] = 0.f; ssq[threadIdx.x] = 0.f; }
    __syncthreads();

    int node = (blockIdx.x * blockDim.x + threadIdx.x) >> 5;
    int lane = threadIdx.x & 31;
    float a0 = 0.f, a1 = 0.f;
    float o0 = 0.f, o1 = 0.f;

    if (node < n) {
        int cn = cnt[node];
        unsigned base = (unsigned)node * BCAP;
        float dc = dinv[node];
        for (int i = 0; i < cn; i += 32) {
            int idx = i + lane;
            int r = 0; float nd = 0.f;
            if (idx < cn) { r = bkt[base + idx]; nd = dinv[r]; }
            int c2 = min(32, cn - i);
            int j = 0;
            // 16-deep: two 8-groups, all 16 loads issued before any consumption
            for (; j + 16 <= c2; j += 16) {
                unsigned rr[16]; float nn[16];
                #pragma unroll
                for (int t = 0; t < 16; t++) {
                    rr[t] = (unsigned)__shfl_sync(0xffffffffu, r, j + t);
                    nn[t] = __shfl_sync(0xffffffffu, nd, j + t);
                }
                float2 v[16];
                #pragma unroll
                for (int t = 0; t < 16; t++) v[t] = ldh2(m + rr[t] * 64 + lane * 2);
                #pragma unroll
                for (int t = 0; t < 16; t++) {
                    a0 = fmaf(nn[t], v[t].x, a0);
                    a1 = fmaf(nn[t], v[t].y, a1);
                }
            }
            for (; j + 8 <= c2; j += 8) {
                unsigned rr[8]; float nn[8];
                #pragma unroll
                for (int t = 0; t < 8; t++) {
                    rr[t] = (unsigned)__shfl_sync(0xffffffffu, r, j + t);
                    nn[t] = __shfl_sync(0xffffffffu, nd, j + t);
                }
                float2 v[8];
                #pragma unroll
                for (int t = 0; t < 8; t++) v[t] = ldh2(m + rr[t] * 64 + lane * 2);
                #pragma unroll
                for (int t = 0; t < 8; t++) {
                    a0 = fmaf(nn[t], v[t].x, a0);
                    a1 = fmaf(nn[t], v[t].y, a1);
                }
            }
            for (; j < c2; j++) {
                unsigned rr = (unsigned)__shfl_sync(0xffffffffu, r, j);
                float nnv = __shfl_sync(0xffffffffu, nd, j);
                float2 v = ldh2(m + rr * 64 + lane * 2);
                a0 = fmaf(nnv, v.x, a0);
                a1 = fmaf(nnv, v.y, a1);
            }
        }
        o0 = a0 * dc; o1 = a1 * dc;
        *(float2*)&agg[(unsigned)node * 64 + lane * 2] = make_float2(o0, o1);
    }

    atomicAdd(&ssum[lane * 2], o0);
    atomicAdd(&ssum[lane * 2 + 1], o1);
    atomicAdd(&ssq[lane * 2], o0 * o0);
    atomicAdd(&ssq[lane * 2 + 1], o1 * o1);
    __syncthreads();
    if (threadIdx.x < 64) {
        atomicAdd(&stats[threadIdx.x], ssum[threadIdx.x]);
        atomicAdd(&stats[64 + threadIdx.x], ssq[threadIdx.x]);
    }
}

// ===== gather layer 1 (m pre-scaled, 16-deep via 8x float4 + staged second batch) =====
__global__ __launch_bounds__(256) void gather128_kernel(const int* __restrict__ cnt,
                                                        const int* __restrict__ bkt,
                                                        const float* __restrict__ dinv,
                                                        const __half* __restrict__ m,
                                                        float* __restrict__ agg,
                                                        float* __restrict__ stats, int n) {
    __shared__ float ssum[128], ssq[128];
    if (threadIdx.x < 128) { ssum[threadIdx.x] = 0.f; ssq[threadIdx.x] = 0.f; }
    __syncthreads();

    int node = (blockIdx.x * blockDim.x + threadIdx.x) >> 5;
    int lane = threadIdx.x & 31;
    float acc[4] = {0.f, 0.f, 0.f, 0.f};
    float out[4] = {0.f, 0.f, 0.f, 0.f};

    if (node < n) {
        int cn = cnt[node];
        unsigned base = (unsigned)node * BCAP;
        float dc = dinv[node];
        for (int i = 0; i < cn; i += 32) {
            int idx = i + lane;
            int r = (idx < cn) ? bkt[base + idx] : 0;
            int c2 = min(32, cn - i);
            int j = 0;
            // 16-deep as raw uint2 words (16*8B = within register budget), convert after
            for (; j + 16 <= c2; j += 16) {
                unsigned rr[16];
                #pragma unroll
                for (int t = 0; t < 16; t++)
                    rr[t] = (unsigned)__shfl_sync(0xffffffffu, r, j + t);
                uint2 w[16];
                #pragma unroll
                for (int t = 0; t < 16; t++)
                    w[t] = *(const uint2*)(m + rr[t] * 128 + lane * 4);
                #pragma unroll
                for (int t = 0; t < 16; t++) {
                    float2 f0 = __half22float2(*(__half2*)&w[t].x);
                    float2 f1 = __half22float2(*(__half2*)&w[t].y);
                    acc[0] += f0.x; acc[1] += f0.y;
                    acc[2] += f1.x; acc[3] += f1.y;
                }
            }
            for (; j + 8 <= c2; j += 8) {
                unsigned rr[8];
                #pragma unroll
                for (int t = 0; t < 8; t++)
                    rr[t] = (unsigned)__shfl_sync(0xffffffffu, r, j + t);
                float4 v[8];
                #pragma unroll
                for (int t = 0; t < 8; t++) v[t] = ldh4(m + rr[t] * 128 + lane * 4);
                #pragma unroll
                for (int t = 0; t < 8; t++) {
                    acc[0] += v[t].x; acc[1] += v[t].y;
                    acc[2] += v[t].z; acc[3] += v[t].w;
                }
            }
            for (; j < c2; j++) {
                unsigned rr = (unsigned)__shfl_sync(0xffffffffu, r, j);
                float4 v = ldh4(m + rr * 128 + lane * 4);
                acc[0] += v.x; acc[1] += v.y; acc[2] += v.z; acc[3] += v.w;
            }
        }
        #pragma unroll
        for (int v = 0; v < 4; v++) out[v] = acc[v] * dc;
        *(float4*)&agg[(unsigned)node * 128 + lane * 4] = make_float4(out[0], out[1], out[2], out[3]);
    }

    #pragma unroll
    for (int v = 0; v < 4; v++) {
        int c = lane * 4 + v;
        atomicAdd(&ssum[c], out[v]);
        atomicAdd(&ssq[c], out[v] * out[v]);
    }
    __syncthreads();
    if (threadIdx.x < 128) {
        atomicAdd(&stats[threadIdx.x], ssum[threadIdx.x]);
        atomicAdd(&stats[128 + threadIdx.x], ssq[threadIdx.x]);
    }
}

// ====== head: fc1+fc2+softmax with inline BN1 finalize for both slices ======
__global__ __launch_bounds__(256) void head_kernel(const float* __restrict__ B,
                                                   const float* __restrict__ bias,
                                                   const float* __restrict__ gam,
                                                   const float* __restrict__ bet,
                                                   const float* __restrict__ W2,
                                                   const float* __restrict__ b2,
                                                   float* __restrict__ out, int n) {
    constexpr int ASTR = 72;
    constexpr int BSTR = 136;
    __shared__ __half  As[128 * ASTR];
    __shared__ unsigned Bs[32 * BSTR];
    __shared__ float slog[256];
    __shared__ float sab[2][256];

    int tid = threadIdx.x;
    int row0 = blockIdx.x * 128;
    int warp = tid >> 5, lane = tid & 31;
    int wr = warp >> 1, wc = warp & 1;
    int rbase = wr * 32, nbase = wc * 64;
    int g = lane >> 2, q = lane & 3;

    slog[tid] = 0.f;
    {
        int s = tid >> 7, c = tid & 127;
        const float* st = &g_stats[s][128];
        float inv_n = 1.f / (float)n;
        float mu = st[c] * inv_n;
        float var = fmaxf(st[128 + c] * inv_n - mu * mu, 0.f);
        float a = gam[c] * rsqrtf(var + 1e-5f);
        sab[s][c] = a;
        sab[s][128 + c] = bet[c] - a * mu;
    }

    float acc[2][8][4];
    #pragma unroll
    for (int mt = 0; mt < 2; mt++)
        #pragma unroll
        for (int nt = 0; nt < 8; nt++)
            #pragma unroll
            for (int e = 0; e < 4; e++) acc[mt][nt][e] = 0.f;

    for (int c = 0; c < 4; c++) {
        __syncthreads();
        int s = c >> 1;
        const float* agg = g_agg1[s];
        const float* prj = g_proj[s];
        const float* ab  = sab[s];
        int kbase = (c & 1) * 64;
        #pragma unroll
        for (int i = 0; i < 16; i++) {
            int idx = tid + 256 * i;
            int r = idx >> 5, kp = idx & 31;
            float v0 = 0.f, v1 = 0.f;
            if (row0 + r < n) {
                int ch = kbase + kp * 2;
                unsigned o = (unsigned)(row0 + r) * 128u + ch;
                float2 av = *(const float2*)&agg[o];
                float2 pv = *(const float2*)&prj[o];
                v0 = san(fmaf(ab[ch], av.x, ab[128 + ch]) + pv.x);
                v1 = san(fmaf(ab[ch + 1], av.y, ab[128 + ch + 1]) + pv.y);
            }
            *(unsigned*)&As[r * ASTR + kp * 2] = h2u(__floats2half2_rn(v0, v1));
        }
        const float* Bc = B + c * 64 * 128;
        #pragma unroll
        for (int i = 0; i < 16; i++) {
            int idx = tid + 256 * i;
            int kp = idx >> 7, nn = idx & 127;
            Bs[kp * BSTR + nn] = h2u(__floats2half2_rn(Bc[(2 * kp) * 128 + nn],
                                                       Bc[(2 * kp + 1) * 128 + nn]));
        }
        __syncthreads();

        #pragma unroll
        for (int kk = 0; kk < 4; kk++) {
            unsigned a[2][4];
            #pragma unroll
            for (int mt = 0; mt < 2; mt++) {
                const __half* ap = &As[(rbase + mt * 16 + g) * ASTR + kk * 16 + q * 2];
                a[mt][0] = *(const unsigned*)ap;
                a[mt][1] = *(const unsigned*)(ap + 8 * ASTR);
                a[mt][2] = *(const unsigned*)(ap + 8);
                a[mt][3] = *(const unsigned*)(ap + 8 * ASTR + 8);
            }
            int kp = kk * 8 + q;
            #pragma unroll
            for (int nt = 0; nt < 8; nt++) {
                int nn = nbase + nt * 8 + g;
                unsigned b0 = Bs[kp * BSTR + nn];
                unsigned b1 = Bs[(kp + 4) * BSTR + nn];
                mma16816(acc[0][nt], a[0], b0, b1);
                mma16816(acc[1][nt], a[1], b0, b1);
            }
        }
    }
    __syncthreads();

    #pragma unroll
    for (int mt = 0; mt < 2; mt++) {
        #pragma unroll
        for (int h = 0; h < 2; h++) {
            int rl = rbase + mt * 16 + g + h * 8;
            float l0 = 0.f, l1 = 0.f;
            #pragma unroll
            for (int nt = 0; nt < 8; nt++) {
                int col = nbase + nt * 8 + q * 2;
                float h0 = fmaxf(acc[mt][nt][h * 2] + bias[col], 0.f);
                float h1 = fmaxf(acc[mt][nt][h * 2 + 1] + bias[col + 1], 0.f);
                l0 = fmaf(h0, W2[col * 2],     fmaf(h1, W2[(col + 1) * 2],     l0));
                l1 = fmaf(h0, W2[col * 2 + 1], fmaf(h1, W2[(col + 1) * 2 + 1], l1));
            }
            atomicAdd(&slog[rl * 2],     l0);
            atomicAdd(&slog[rl * 2 + 1], l1);
        }
    }
    __syncthreads();

    if (tid < 128) {
        int r = row0 + tid;
        if (r < n) {
            float l0 = slog[tid * 2] + b2[0];
            float l1 = slog[tid * 2 + 1] + b2[1];
            float mx = fmaxf(l0, l1);
            float e0 = expf(l0 - mx), e1 = expf(l1 - mx);
            float inv = 1.f / (e0 + e1);
            *(float2*)&out[(size_t)r * 2] = make_float2(l0, l1);
            *(float2*)&out[(size_t)2 * n + r * 2] = make_float2(e0 * inv, e1 * inv);
        }
    }
}

// ---------------- host launch (two streams per slice, graph-capturable) ----------------
extern "C" void kernel_launch(void* const* d_in, const int* in_sizes, int n_in,
                              void* d_out, int out_size) {
    const float* x     = (const float*)d_in[0];
    const int*   ei[2] = {(const int*)d_in[1], (const int*)d_in[2]};
    const float* w0[2]   = {(const float*)d_in[3], (const float*)d_in[8]};
    const float* w1[2]   = {(const float*)d_in[5], (const float*)d_in[10]};
    const float* res1[2] = {(const float*)d_in[7], (const float*)d_in[12]};
    const float* bn_g0 = (const float*)d_in[13];
    const float* bn_b0 = (const float*)d_in[14];
    const float* bn_g1 = (const float*)d_in[15];
    const float* bn_b1 = (const float*)d_in[16];
    const float* fc1_w = (const float*)d_in[17];
    const float* fc1_b = (const float*)d_in[18];
    const float* fc2_w = (const float*)d_in[19];
    const float* fc2_b = (const float*)d_in[20];

    int n = in_sizes[0] / 64;
    int E = in_sizes[1] / 2;

    float *dinv_p[2], *agg0_p[2], *agg1_p[2], *proj_p[2], *stats_p[2];
    __half* m_p[2];
    int *cnt_p[2], *bkt_p[2];
    {
        char* base;
        cudaGetSymbolAddress((void**)&base, g_dinv);
        dinv_p[0] = (float*)base; dinv_p[1] = dinv_p[0] + MAXN;
        cudaGetSymbolAddress((void**)&base, g_cnt);
        cnt_p[0] = (int*)base; cnt_p[1] = cnt_p[0] + MAXN;
        cudaGetSymbolAddress((void**)&base, g_bkt);
        bkt_p[0] = (int*)base; bkt_p[1] = bkt_p[0] + (size_t)MAXN * BCAP;
        cudaGetSymbolAddress((void**)&base, g_m);
        m_p[0] = (__half*)base; m_p[1] = m_p[0] + (size_t)MAXN * 128;
        cudaGetSymbolAddress((void**)&base, g_agg0);
        agg0_p[0] = (float*)base; agg0_p[1] = agg0_p[0] + (size_t)MAXN * 64;
        cudaGetSymbolAddress((void**)&base, g_agg1);
        agg1_p[0] = (float*)base; agg1_p[1] = agg1_p[0] + (size_t)MAXN * 128;
        cudaGetSymbolAddress((void**)&base, g_proj);
        proj_p[0] = (float*)base; proj_p[1] = proj_p[0] + (size_t)MAXN * 128;
        cudaGetSymbolAddress((void**)&base, g_stats);
        stats_p[0] = (float*)base; stats_p[1] = stats_p[0] + 392;
    }

    int ebl  = (E + 255) / 256;
    int nbl  = (n + 255) / 256;
    int hbl  = (n + 127) / 128;   // 128-row gemm blocks
    int g1bl = (n + 63) / 64;     // merged layer-1 gemm blocks
    int wbl  = (n + 7) / 8;       // warp-per-node gathers

    cudaEventRecord(g_ev[0], 0);

    for (int s = 0; s < 2; s++) {
        cudaStream_t a = g_str[2 * s];
        cudaStream_t b = g_str[2 * s + 1];
        cudaEvent_t evG0   = g_ev[1 + 2 * s];
        cudaEvent_t evDone = g_ev[2 + 2 * s];

        cudaStreamWaitEvent(a, g_ev[0], 0);
        cudaStreamWaitEvent(b, g_ev[0], 0);

        // stream a: single-pass bucketed CSR, then dinv (+full stats zero)
        cudaMemsetAsync(cnt_p[s], 0, n * sizeof(int), a);
        fill_kernel<<<ebl, 256, 0, a>>>(ei[s], cnt_p[s], bkt_p[s], E);
        dinv_kernel<<<nbl, 256, 0, a>>>(cnt_p[s], dinv_p[s], stats_p[s], n);

        // stream b: layer-0 GEMM (unscaled fp16; zero dependencies -> starts at t=0)
        hgemm0_kernel<<<hbl, 256, 0, b>>>(x, w0[s], m_p[s], n);
        cudaEventRecord(evG0, b);

        // join: gather layer 0 (warp/node, 16-deep, per-edge dinv + fused BN stats)
        cudaStreamWaitEvent(a, evG0, 0);
        gather64_kernel<<<wbl, 256, 0, a>>>(cnt_p[s], bkt_p[s], dinv_p[s], m_p[s],
                                            agg0_p[s], stats_p[s], n);

        // merged layer-1 GEMM: m1 (fp16*dinv) + proj (fp32) in one pass (inline BN0)
        hgemm1m_kernel<<<g1bl, 256, 0, a>>>(agg0_p[s], x, stats_p[s], bn_g0, bn_b0,
                                            w1[s], res1[s], dinv_p[s],
                                            m_p[s], proj_p[s], n);

        // gather layer 1 (pre-scaled m1, 16-deep + fused BN stats)
        gather128_kernel<<<wbl, 256, 0, a>>>(cnt_p[s], bkt_p[s], dinv_p[s], m_p[s],
                                             agg1_p[s], stats_p[s] + 128, n);
        cudaEventRecord(evDone, a);
    }

    // join both slices back to origin stream; fused head (inline BN1 finalize)
    cudaStreamWaitEvent(0, g_ev[2], 0);
    cudaStreamWaitEvent(0, g_ev[4], 0);
    head_kernel<<<hbl, 256>>>(fc1_w, fc1_b, bn_g1, bn_b1, fc2_w, fc2_b, (float*)d_out, n);
}

// round 16
// speedup vs baseline: 1.0490x; 1.0490x over previous
#include <cuda_runtime.h>
#include <cuda_bf16.h>
#include <cuda_fp16.h>
#include <math.h>

#define MAXN 50048           // divisible by 16
#define BCAP 128             // bucket capacity per node (in-degree ~Poisson(32), max ~58)
#define MAXE 1600000

// ---------------- per-slice device scratch (static; no allocations) ----------------
__device__ __align__(16) float  g_dinv[2][MAXN];
__device__ __align__(16) int    g_cnt[2][MAXN];
__device__ __align__(16) int    g_bkt[2][(size_t)MAXN * BCAP];
__device__ __align__(16) __half g_m[2][(size_t)MAXN * 128];     // L0: unscaled; L1: dinv-prescaled
__device__ __align__(16) float  g_agg0[2][(size_t)MAXN * 64];
__device__ __align__(16) float  g_agg1[2][(size_t)MAXN * 128];
__device__ __align__(16) float  g_proj[2][(size_t)MAXN * 128];
// per slice: [0,128) stats layer0 (sum,sq F=64); [128,384) layer1 (F=128)
__device__ __align__(16) float  g_stats[2][392];

// ---------------- static streams / events (host-side, created at load) ----------------
static cudaStream_t g_str[4];
static cudaEvent_t  g_ev[10];
static int g_init_streams = []() {
    for (int i = 0; i < 4; i++) cudaStreamCreateWithFlags(&g_str[i], cudaStreamNonBlocking);
    for (int i = 0; i < 10; i++) cudaEventCreateWithFlags(&g_ev[i], cudaEventDisableTiming);
    return 0;
}();

// nan_to_num(nan=0, posinf=100, neginf=-100)
__device__ __forceinline__ float san(float v) {
    if (isnan(v)) return 0.f;
    if (isinf(v)) return v > 0.f ? 100.f : -100.f;
    return v;
}

__device__ __forceinline__ unsigned h2u(__half2 h) { return *(unsigned*)&h; }

__device__ __forceinline__ float4 ldh4(const __half* p) {
    uint2 w = *(const uint2*)p;
    float2 a = __half22float2(*(__half2*)&w.x);
    float2 b = __half22float2(*(__half2*)&w.y);
    return make_float4(a.x, a.y, b.x, b.y);
}
__device__ __forceinline__ float2 ldh2(const __half* p) {
    return __half22float2(*(const __half2*)p);
}

// m16n8k16 f16xf16 -> f32 accumulate
__device__ __forceinline__ void mma16816(float* c, const unsigned* a, unsigned b0, unsigned b1) {
    asm volatile(
        "mma.sync.aligned.m16n8k16.row.col.f32.f16.f16.f32 "
        "{%0,%1,%2,%3}, {%4,%5,%6,%7}, {%8,%9}, {%0,%1,%2,%3};"
        : "+f"(c[0]), "+f"(c[1]), "+f"(c[2]), "+f"(c[3])
        : "r"(a[0]), "r"(a[1]), "r"(a[2]), "r"(a[3]), "r"(b0), "r"(b1));
}

// ---------------- single-pass bucketed CSR fill ----------------
__global__ void fill_kernel(const int* __restrict__ ei, int* __restrict__ cnt,
                            int* __restrict__ bkt, int E) {
    int e = blockIdx.x * blockDim.x + threadIdx.x;
    if (e < E) {
        int c = ei[E + e];
        int pos = atomicAdd(&cnt[c], 1);
        bkt[(unsigned)c * BCAP + pos] = ei[e];
    }
}

// dinv[i] = rsqrt(cnt[i]); block 0 also zeroes ALL 392 BN-stats words (strided)
__global__ void dinv_kernel(const int* __restrict__ cnt, float* __restrict__ dinv,
                            float* __restrict__ stats, int n) {
    int i = blockIdx.x * blockDim.x + threadIdx.x;
    if (blockIdx.x == 0) {
        for (int j = threadIdx.x; j < 392; j += 256) stats[j] = 0.f;
    }
    if (i < n) {
        int d = cnt[i];
        dinv[i] = d > 0 ? rsqrtf((float)d) : 0.f;
    }
}

// ================= HMMA GEMM (layer 0): C[128,64] = A[*,64] @ B[64,64], fp16 out ======
__global__ __launch_bounds__(256) void hgemm0_kernel(const float* __restrict__ A,
                                                     const float* __restrict__ B,
                                                     __half* __restrict__ C, int n) {
    constexpr int ASTR = 72;
    constexpr int BSTR = 72;
    __shared__ __half  As[128 * ASTR];
    __shared__ unsigned Bs[32 * BSTR];

    int tid = threadIdx.x;
    int row0 = blockIdx.x * 128;

    #pragma unroll
    for (int i = 0; i < 16; i++) {
        int idx = tid + 256 * i;
        int r = idx >> 5, kp = idx & 31;
        float v0 = 0.f, v1 = 0.f;
        if (row0 + r < n) {
            unsigned o = (unsigned)(row0 + r) * 64u + kp * 2;
            float2 av = *(const float2*)&A[o];
            v0 = av.x; v1 = av.y;
        }
        *(unsigned*)&As[r * ASTR + kp * 2] = h2u(__floats2half2_rn(v0, v1));
    }
    #pragma unroll
    for (int i = 0; i < 8; i++) {
        int idx = tid + 256 * i;
        int kp = idx >> 6, nn = idx & 63;
        Bs[kp * BSTR + nn] = h2u(__floats2half2_rn(B[(2 * kp) * 64 + nn],
                                                   B[(2 * kp + 1) * 64 + nn]));
    }
    __syncthreads();

    int warp = tid >> 5, lane = tid & 31;
    int wr = warp >> 1, wc = warp & 1;
    int rbase = wr * 32, nbase = wc * 32;
    int g = lane >> 2, q = lane & 3;

    float acc[2][4][4];
    #pragma unroll
    for (int mt = 0; mt < 2; mt++)
        #pragma unroll
        for (int nt = 0; nt < 4; nt++)
            #pragma unroll
            for (int e = 0; e < 4; e++) acc[mt][nt][e] = 0.f;

    #pragma unroll
    for (int kk = 0; kk < 4; kk++) {
        unsigned a[2][4];
        #pragma unroll
        for (int mt = 0; mt < 2; mt++) {
            const __half* ap = &As[(rbase + mt * 16 + g) * ASTR + kk * 16 + q * 2];
            a[mt][0] = *(const unsigned*)ap;
            a[mt][1] = *(const unsigned*)(ap + 8 * ASTR);
            a[mt][2] = *(const unsigned*)(ap + 8);
            a[mt][3] = *(const unsigned*)(ap + 8 * ASTR + 8);
        }
        int kp = kk * 8 + q;
        #pragma unroll
        for (int nt = 0; nt < 4; nt++) {
            int nn = nbase + nt * 8 + g;
            unsigned b0 = Bs[kp * BSTR + nn];
            unsigned b1 = Bs[(kp + 4) * BSTR + nn];
            mma16816(acc[0][nt], a[0], b0, b1);
            mma16816(acc[1][nt], a[1], b0, b1);
        }
    }

    #pragma unroll
    for (int mt = 0; mt < 2; mt++) {
        #pragma unroll
        for (int h = 0; h < 2; h++) {
            int r = row0 + rbase + mt * 16 + g + h * 8;
            if (r < n) {
                #pragma unroll
                for (int nt = 0; nt < 4; nt++) {
                    float c0 = acc[mt][nt][h * 2], c1 = acc[mt][nt][h * 2 + 1];
                    int col = nbase + nt * 8 + q * 2;
                    *(unsigned*)&C[(unsigned)r * 64 + col] = h2u(__floats2half2_rn(c0, c1));
                }
            }
        }
    }
}

// ====== merged layer-1 GEMM: one A pass -> m1 (fp16*dinv) + proj (fp32); inline BN0 ======
__global__ __launch_bounds__(256) void hgemm1m_kernel(const float* __restrict__ agg0,
                                                      const float* __restrict__ x,
                                                      const float* __restrict__ stats,
                                                      const float* __restrict__ gam,
                                                      const float* __restrict__ bet,
                                                      const float* __restrict__ W1,
                                                      const float* __restrict__ R1,
                                                      const float* __restrict__ dinv,
                                                      __half* __restrict__ mOut,
                                                      float* __restrict__ projOut, int n) {
    constexpr int ASTR = 72;
    constexpr int BSTR = 264;
    __shared__ __half  As[64 * ASTR];
    __shared__ unsigned Bs[32 * BSTR];
    __shared__ float sab[128];

    int tid = threadIdx.x;
    int row0 = blockIdx.x * 64;

    if (tid < 64) {
        int c = tid;
        float inv_n = 1.f / (float)n;
        float mu = stats[c] * inv_n;
        float var = fmaxf(stats[64 + c] * inv_n - mu * mu, 0.f);
        float a = gam[c] * rsqrtf(var + 1e-5f);
        sab[c] = a;
        sab[64 + c] = bet[c] - a * mu;
    }
    __syncthreads();

    #pragma unroll
    for (int i = 0; i < 8; i++) {
        int idx = tid + 256 * i;
        int r = idx >> 5, kp = idx & 31;
        float v0 = 0.f, v1 = 0.f;
        if (row0 + r < n) {
            unsigned o = (unsigned)(row0 + r) * 64u + kp * 2;
            float2 av = *(const float2*)&agg0[o];
            float2 xv = *(const float2*)&x[o];
            float t0 = fmaf(sab[kp * 2], av.x, sab[64 + kp * 2]);
            float t1 = fmaf(sab[kp * 2 + 1], av.y, sab[64 + kp * 2 + 1]);
            v0 = san(fmaxf(t0, 0.f) + xv.x);
            v1 = san(fmaxf(t1, 0.f) + xv.y);
        }
        *(unsigned*)&As[r * ASTR + kp * 2] = h2u(__floats2half2_rn(v0, v1));
    }
    #pragma unroll
    for (int i = 0; i < 32; i++) {
        int idx = tid + 256 * i;
        int kp = idx >> 8, nn = idx & 255;
        float b0, b1;
        if (nn < 128) {
            b0 = W1[(2 * kp) * 128 + nn];
            b1 = W1[(2 * kp + 1) * 128 + nn];
        } else {
            b0 = R1[(2 * kp) * 128 + nn - 128];
            b1 = R1[(2 * kp + 1) * 128 + nn - 128];
        }
        Bs[kp * BSTR + nn] = h2u(__floats2half2_rn(b0, b1));
    }
    __syncthreads();

    int warp = tid >> 5, lane = tid & 31;
    int wr = warp >> 2, wc = warp & 3;
    int rbase = wr * 32, nbase = wc * 64;
    int g = lane >> 2, q = lane & 3;

    float acc[2][8][4];
    #pragma unroll
    for (int mt = 0; mt < 2; mt++)
        #pragma unroll
        for (int nt = 0; nt < 8; nt++)
            #pragma unroll
            for (int e = 0; e < 4; e++) acc[mt][nt][e] = 0.f;

    #pragma unroll
    for (int kk = 0; kk < 4; kk++) {
        unsigned a[2][4];
        #pragma unroll
        for (int mt = 0; mt < 2; mt++) {
            const __half* ap = &As[(rbase + mt * 16 + g) * ASTR + kk * 16 + q * 2];
            a[mt][0] = *(const unsigned*)ap;
            a[mt][1] = *(const unsigned*)(ap + 8 * ASTR);
            a[mt][2] = *(const unsigned*)(ap + 8);
            a[mt][3] = *(const unsigned*)(ap + 8 * ASTR + 8);
        }
        int kp = kk * 8 + q;
        #pragma unroll
        for (int nt = 0; nt < 8; nt++) {
            int nn = nbase + nt * 8 + g;
            unsigned b0 = Bs[kp * BSTR + nn];
            unsigned b1 = Bs[(kp + 4) * BSTR + nn];
            mma16816(acc[0][nt], a[0], b0, b1);
            mma16816(acc[1][nt], a[1], b0, b1);
        }
    }

    bool isM = (nbase < 128);
    #pragma unroll
    for (int mt = 0; mt < 2; mt++) {
        #pragma unroll
        for (int h = 0; h < 2; h++) {
            int r = row0 + rbase + mt * 16 + g + h * 8;
            if (r < n) {
                if (isM) {
                    float sc = dinv[r];
                    #pragma unroll
                    for (int nt = 0; nt < 8; nt++) {
                        float c0 = acc[mt][nt][h * 2] * sc, c1 = acc[mt][nt][h * 2 + 1] * sc;
                        int col = nbase + nt * 8 + q * 2;
                        *(unsigned*)&mOut[(unsigned)r * 128 + col] = h2u(__floats2half2_rn(c0, c1));
                    }
                } else {
                    #pragma unroll
                    for (int nt = 0; nt < 8; nt++) {
                        float c0 = acc[mt][nt][h * 2], c1 = acc[mt][nt][h * 2 + 1];
                        int col = nbase + nt * 8 + q * 2 - 128;
                        *(float2*)&projOut[(unsigned)r * 128 + col] = make_float2(c0, c1);
                    }
                }
            }
        }
    }
}

// ===== gather layer 0 (exact R13 form, 8-deep): per-edge dinv + fused BN stats =====
__global__ __launch_bounds__(256) void gather64_kernel(const int* __restrict__ cnt,
                                                       const int* __restrict__ bkt,
                                                       const float* __restrict__ dinv,
                                                       const __half* __restrict__ m,
                                                       float* __restrict__ agg,
                                                       float* __restrict__ stats, int n) {
    __shared__ float ssum[64], ssq[64];
    if (threadIdx.x < 64) { ssum[threadIdx.x] = 0.f; ssq[threadIdx.x] = 0.f; }
    __syncthreads();

    int node = (blockIdx.x * blockDim.x + threadIdx.x) >> 5;
    int lane = threadIdx.x & 31;
    float a0 = 0.f, a1 = 0.f;
    float o0 = 0.f, o1 = 0.f;

    if (node < n) {
        int cn = cnt[node];
        unsigned base = (unsigned)node * BCAP;
        float dc = dinv[node];
        for (int i = 0; i < cn; i += 32) {
            int idx = i + lane;
            int r = 0; float nd = 0.f;
            if (idx < cn) { r = bkt[base + idx]; nd = dinv[r]; }
            int c2 = min(32, cn - i);
            int j = 0;
            for (; j + 8 <= c2; j += 8) {
                unsigned rr[8]; float nn[8];
                #pragma unroll
                for (int t = 0; t < 8; t++) {
                    rr[t] = (unsigned)__shfl_sync(0xffffffffu, r, j + t);
                    nn[t] = __shfl_sync(0xffffffffu, nd, j + t);
                }
                float2 v[8];
                #pragma unroll
                for (int t = 0; t < 8; t++) v[t] = ldh2(m + rr[t] * 64 + lane * 2);
                #pragma unroll
                for (int t = 0; t < 8; t++) {
                    a0 = fmaf(nn[t], v[t].x, a0);
                    a1 = fmaf(nn[t], v[t].y, a1);
                }
            }
            for (; j < c2; j++) {
                unsigned rr = (unsigned)__shfl_sync(0xffffffffu, r, j);
                float nnv = __shfl_sync(0xffffffffu, nd, j);
                float2 v = ldh2(m + rr * 64 + lane * 2);
                a0 = fmaf(nnv, v.x, a0);
                a1 = fmaf(nnv, v.y, a1);
            }
        }
        o0 = a0 * dc; o1 = a1 * dc;
        *(float2*)&agg[(unsigned)node * 64 + lane * 2] = make_float2(o0, o1);
    }

    atomicAdd(&ssum[lane * 2], o0);
    atomicAdd(&ssum[lane * 2 + 1], o1);
    atomicAdd(&ssq[lane * 2], o0 * o0);
    atomicAdd(&ssq[lane * 2 + 1], o1 * o1);
    __syncthreads();
    if (threadIdx.x < 64) {
        atomicAdd(&stats[threadIdx.x], ssum[threadIdx.x]);
        atomicAdd(&stats[64 + threadIdx.x], ssq[threadIdx.x]);
    }
}

// ===== gather layer 1 (exact R13 form, 8-deep, m pre-scaled) + fused BN stats =====
__global__ __launch_bounds__(256) void gather128_kernel(const int* __restrict__ cnt,
                                                        const int* __restrict__ bkt,
                                                        const float* __restrict__ dinv,
                                                        const __half* __restrict__ m,
                                                        float* __restrict__ agg,
                                                        float* __restrict__ stats, int n) {
    __shared__ float ssum[128], ssq[128];
    if (threadIdx.x < 128) { ssum[threadIdx.x] = 0.f; ssq[threadIdx.x] = 0.f; }
    __syncthreads();

    int node = (blockIdx.x * blockDim.x + threadIdx.x) >> 5;
    int lane = threadIdx.x & 31;
    float acc[4] = {0.f, 0.f, 0.f, 0.f};
    float out[4] = {0.f, 0.f, 0.f, 0.f};

    if (node < n) {
        int cn = cnt[node];
        unsigned base = (unsigned)node * BCAP;
        float dc = dinv[node];
        for (int i = 0; i < cn; i += 32) {
            int idx = i + lane;
            int r = (idx < cn) ? bkt[base + idx] : 0;
            int c2 = min(32, cn - i);
            int j = 0;
            for (; j + 8 <= c2; j += 8) {
                unsigned rr[8];
                #pragma unroll
                for (int t = 0; t < 8; t++)
                    rr[t] = (unsigned)__shfl_sync(0xffffffffu, r, j + t);
                float4 v[8];
                #pragma unroll
                for (int t = 0; t < 8; t++) v[t] = ldh4(m + rr[t] * 128 + lane * 4);
                #pragma unroll
                for (int t = 0; t < 8; t++) {
                    acc[0] += v[t].x; acc[1] += v[t].y;
                    acc[2] += v[t].z; acc[3] += v[t].w;
                }
            }
            for (; j < c2; j++) {
                unsigned rr = (unsigned)__shfl_sync(0xffffffffu, r, j);
                float4 v = ldh4(m + rr * 128 + lane * 4);
                acc[0] += v.x; acc[1] += v.y; acc[2] += v.z; acc[3] += v.w;
            }
        }
        #pragma unroll
        for (int v = 0; v < 4; v++) out[v] = acc[v] * dc;
        *(float4*)&agg[(unsigned)node * 128 + lane * 4] = make_float4(out[0], out[1], out[2], out[3]);
    }

    #pragma unroll
    for (int v = 0; v < 4; v++) {
        int c = lane * 4 + v;
        atomicAdd(&ssum[c], out[v]);
        atomicAdd(&ssq[c], out[v] * out[v]);
    }
    __syncthreads();
    if (threadIdx.x < 128) {
        atomicAdd(&stats[threadIdx.x], ssum[threadIdx.x]);
        atomicAdd(&stats[128 + threadIdx.x], ssq[threadIdx.x]);
    }
}

// ====== head: fc1+fc2+softmax with inline BN1 finalize for both slices ======
__global__ __launch_bounds__(256) void head_kernel(const float* __restrict__ B,
                                                   const float* __restrict__ bias,
                                                   const float* __restrict__ gam,
                                                   const float* __restrict__ bet,
                                                   const float* __restrict__ W2,
                                                   const float* __restrict__ b2,
                                                   float* __restrict__ out, int n) {
    constexpr int ASTR = 72;
    constexpr int BSTR = 136;
    __shared__ __half  As[128 * ASTR];
    __shared__ unsigned Bs[32 * BSTR];
    __shared__ float slog[256];
    __shared__ float sab[2][256];

    int tid = threadIdx.x;
    int row0 = blockIdx.x * 128;
    int warp = tid >> 5, lane = tid & 31;
    int wr = warp >> 1, wc = warp & 1;
    int rbase = wr * 32, nbase = wc * 64;
    int g = lane >> 2, q = lane & 3;

    slog[tid] = 0.f;
    {
        int s = tid >> 7, c = tid & 127;
        const float* st = &g_stats[s][128];
        float inv_n = 1.f / (float)n;
        float mu = st[c] * inv_n;
        float var = fmaxf(st[128 + c] * inv_n - mu * mu, 0.f);
        float a = gam[c] * rsqrtf(var + 1e-5f);
        sab[s][c] = a;
        sab[s][128 + c] = bet[c] - a * mu;
    }

    float acc[2][8][4];
    #pragma unroll
    for (int mt = 0; mt < 2; mt++)
        #pragma unroll
        for (int nt = 0; nt < 8; nt++)
            #pragma unroll
            for (int e = 0; e < 4; e++) acc[mt][nt][e] = 0.f;

    for (int c = 0; c < 4; c++) {
        __syncthreads();
        int s = c >> 1;
        const float* agg = g_agg1[s];
        const float* prj = g_proj[s];
        const float* ab  = sab[s];
        int kbase = (c & 1) * 64;
        #pragma unroll
        for (int i = 0; i < 16; i++) {
            int idx = tid + 256 * i;
            int r = idx >> 5, kp = idx & 31;
            float v0 = 0.f, v1 = 0.f;
            if (row0 + r < n) {
                int ch = kbase + kp * 2;
                unsigned o = (unsigned)(row0 + r) * 128u + ch;
                float2 av = *(const float2*)&agg[o];
                float2 pv = *(const float2*)&prj[o];
                v0 = san(fmaf(ab[ch], av.x, ab[128 + ch]) + pv.x);
                v1 = san(fmaf(ab[ch + 1], av.y, ab[128 + ch + 1]) + pv.y);
            }
            *(unsigned*)&As[r * ASTR + kp * 2] = h2u(__floats2half2_rn(v0, v1));
        }
        const float* Bc = B + c * 64 * 128;
        #pragma unroll
        for (int i = 0; i < 16; i++) {
            int idx = tid + 256 * i;
            int kp = idx >> 7, nn = idx & 127;
            Bs[kp * BSTR + nn] = h2u(__floats2half2_rn(Bc[(2 * kp) * 128 + nn],
                                                       Bc[(2 * kp + 1) * 128 + nn]));
        }
        __syncthreads();

        #pragma unroll
        for (int kk = 0; kk < 4; kk++) {
            unsigned a[2][4];
            #pragma unroll
            for (int mt = 0; mt < 2; mt++) {
                const __half* ap = &As[(rbase + mt * 16 + g) * ASTR + kk * 16 + q * 2];
                a[mt][0] = *(const unsigned*)ap;
                a[mt][1] = *(const unsigned*)(ap + 8 * ASTR);
                a[mt][2] = *(const unsigned*)(ap + 8);
                a[mt][3] = *(const unsigned*)(ap + 8 * ASTR + 8);
            }
            int kp = kk * 8 + q;
            #pragma unroll
            for (int nt = 0; nt < 8; nt++) {
                int nn = nbase + nt * 8 + g;
                unsigned b0 = Bs[kp * BSTR + nn];
                unsigned b1 = Bs[(kp + 4) * BSTR + nn];
                mma16816(acc[0][nt], a[0], b0, b1);
                mma16816(acc[1][nt], a[1], b0, b1);
            }
        }
    }
    __syncthreads();

    #pragma unroll
    for (int mt = 0; mt < 2; mt++) {
        #pragma unroll
        for (int h = 0; h < 2; h++) {
            int rl = rbase + mt * 16 + g + h * 8;
            float l0 = 0.f, l1 = 0.f;
            #pragma unroll
            for (int nt = 0; nt < 8; nt++) {
                int col = nbase + nt * 8 + q * 2;
                float h0 = fmaxf(acc[mt][nt][h * 2] + bias[col], 0.f);
                float h1 = fmaxf(acc[mt][nt][h * 2 + 1] + bias[col + 1], 0.f);
                l0 = fmaf(h0, W2[col * 2],     fmaf(h1, W2[(col + 1) * 2],     l0));
                l1 = fmaf(h0, W2[col * 2 + 1], fmaf(h1, W2[(col + 1) * 2 + 1], l1));
            }
            atomicAdd(&slog[rl * 2],     l0);
            atomicAdd(&slog[rl * 2 + 1], l1);
        }
    }
    __syncthreads();

    if (tid < 128) {
        int r = row0 + tid;
        if (r < n) {
            float l0 = slog[tid * 2] + b2[0];
            float l1 = slog[tid * 2 + 1] + b2[1];
            float mx = fmaxf(l0, l1);
            float e0 = expf(l0 - mx), e1 = expf(l1 - mx);
            float inv = 1.f / (e0 + e1);
            *(float2*)&out[(size_t)r * 2] = make_float2(l0, l1);
            *(float2*)&out[(size_t)2 * n + r * 2] = make_float2(e0 * inv, e1 * inv);
        }
    }
}

// ---------------- host launch (two streams per slice, graph-capturable) ----------------
extern "C" void kernel_launch(void* const* d_in, const int* in_sizes, int n_in,
                              void* d_out, int out_size) {
    const float* x     = (const float*)d_in[0];
    const int*   ei[2] = {(const int*)d_in[1], (const int*)d_in[2]};
    const float* w0[2]   = {(const float*)d_in[3], (const float*)d_in[8]};
    const float* w1[2]   = {(const float*)d_in[5], (const float*)d_in[10]};
    const float* res1[2] = {(const float*)d_in[7], (const float*)d_in[12]};
    const float* bn_g0 = (const float*)d_in[13];
    const float* bn_b0 = (const float*)d_in[14];
    const float* bn_g1 = (const float*)d_in[15];
    const float* bn_b1 = (const float*)d_in[16];
    const float* fc1_w = (const float*)d_in[17];
    const float* fc1_b = (const float*)d_in[18];
    const float* fc2_w = (const float*)d_in[19];
    const float* fc2_b = (const float*)d_in[20];

    int n = in_sizes[0] / 64;
    int E = in_sizes[1] / 2;

    float *dinv_p[2], *agg0_p[2], *agg1_p[2], *proj_p[2], *stats_p[2];
    __half* m_p[2];
    int *cnt_p[2], *bkt_p[2];
    {
        char* base;
        cudaGetSymbolAddress((void**)&base, g_dinv);
        dinv_p[0] = (float*)base; dinv_p[1] = dinv_p[0] + MAXN;
        cudaGetSymbolAddress((void**)&base, g_cnt);
        cnt_p[0] = (int*)base; cnt_p[1] = cnt_p[0] + MAXN;
        cudaGetSymbolAddress((void**)&base, g_bkt);
        bkt_p[0] = (int*)base; bkt_p[1] = bkt_p[0] + (size_t)MAXN * BCAP;
        cudaGetSymbolAddress((void**)&base, g_m);
        m_p[0] = (__half*)base; m_p[1] = m_p[0] + (size_t)MAXN * 128;
        cudaGetSymbolAddress((void**)&base, g_agg0);
        agg0_p[0] = (float*)base; agg0_p[1] = agg0_p[0] + (size_t)MAXN * 64;
        cudaGetSymbolAddress((void**)&base, g_agg1);
        agg1_p[0] = (float*)base; agg1_p[1] = agg1_p[0] + (size_t)MAXN * 128;
        cudaGetSymbolAddress((void**)&base, g_proj);
        proj_p[0] = (float*)base; proj_p[1] = proj_p[0] + (size_t)MAXN * 128;
        cudaGetSymbolAddress((void**)&base, g_stats);
        stats_p[0] = (float*)base; stats_p[1] = stats_p[0] + 392;
    }

    int ebl  = (E + 255) / 256;
    int nbl  = (n + 255) / 256;
    int hbl  = (n + 127) / 128;   // 128-row gemm blocks
    int g1bl = (n + 63) / 64;     // merged layer-1 gemm blocks
    int wbl  = (n + 7) / 8;       // warp-per-node gathers

    cudaEventRecord(g_ev[0], 0);

    for (int s = 0; s < 2; s++) {
        cudaStream_t a = g_str[2 * s];
        cudaStream_t b = g_str[2 * s + 1];
        cudaEvent_t evG0   = g_ev[1 + 2 * s];
        cudaEvent_t evDone = g_ev[2 + 2 * s];

        cudaStreamWaitEvent(a, g_ev[0], 0);
        cudaStreamWaitEvent(b, g_ev[0], 0);

        // stream a: single-pass bucketed CSR, then dinv (+full stats zero)
        cudaMemsetAsync(cnt_p[s], 0, n * sizeof(int), a);
        fill_kernel<<<ebl, 256, 0, a>>>(ei[s], cnt_p[s], bkt_p[s], E);
        dinv_kernel<<<nbl, 256, 0, a>>>(cnt_p[s], dinv_p[s], stats_p[s], n);

        // stream b: layer-0 GEMM (unscaled fp16; zero dependencies -> starts at t=0)
        hgemm0_kernel<<<hbl, 256, 0, b>>>(x, w0[s], m_p[s], n);
        cudaEventRecord(evG0, b);

        // join: gather layer 0 (R13 form: warp/node, 8-deep, per-edge dinv + BN stats)
        cudaStreamWaitEvent(a, evG0, 0);
        gather64_kernel<<<wbl, 256, 0, a>>>(cnt_p[s], bkt_p[s], dinv_p[s], m_p[s],
                                            agg0_p[s], stats_p[s], n);

        // merged layer-1 GEMM: m1 (fp16*dinv) + proj (fp32) in one pass (inline BN0)
        hgemm1m_kernel<<<g1bl, 256, 0, a>>>(agg0_p[s], x, stats_p[s], bn_g0, bn_b0,
                                            w1[s], res1[s], dinv_p[s],
                                            m_p[s], proj_p[s], n);

        // gather layer 1 (R13 form, pre-scaled m1 + fused BN stats)
        gather128_kernel<<<wbl, 256, 0, a>>>(cnt_p[s], bkt_p[s], dinv_p[s], m_p[s],
                                             agg1_p[s], stats_p[s] + 128, n);
        cudaEventRecord(evDone, a);
    }

    // join both slices back to origin stream; fused head (inline BN1 finalize)
    cudaStreamWaitEvent(0, g_ev[2], 0);
    cudaStreamWaitEvent(0, g_ev[4], 0);
    head_kernel<<<hbl, 256>>>(fc1_w, fc1_b, bn_g1, bn_b1, fc2_w, fc2_b, (float*)d_out, n);
}

// round 17
// speedup vs baseline: 1.0846x; 1.0339x over previous
#include <cuda_runtime.h>
#include <cuda_bf16.h>
#include <cuda_fp16.h>
#include <math.h>

#define MAXN 50048           // divisible by 16
#define BCAP 128             // bucket capacity per node (in-degree ~Poisson(32), max ~58)
#define MAXE 1600000

// ---------------- per-slice device scratch (static; no allocations) ----------------
__device__ __align__(16) float  g_dinv[2][MAXN];
__device__ __align__(16) int    g_cnt[2][MAXN];
__device__ __align__(16) int    g_bkt[2][(size_t)MAXN * BCAP];
__device__ __align__(16) __half g_m[2][(size_t)MAXN * 128];     // both layers: dinv-prescaled
__device__ __align__(16) float  g_agg0[2][(size_t)MAXN * 64];
__device__ __align__(16) float  g_agg1[2][(size_t)MAXN * 128];
__device__ __align__(16) float  g_proj[2][(size_t)MAXN * 128];
// per slice: [0,128) stats layer0 (sum,sq F=64); [128,384) layer1 (F=128)
__device__ __align__(16) float  g_stats[2][392];

// ---------------- static streams / events (host-side, created at load) ----------------
static cudaStream_t g_str[4];
static cudaEvent_t  g_ev[10];
static int g_init_streams = []() {
    for (int i = 0; i < 4; i++) cudaStreamCreateWithFlags(&g_str[i], cudaStreamNonBlocking);
    for (int i = 0; i < 10; i++) cudaEventCreateWithFlags(&g_ev[i], cudaEventDisableTiming);
    return 0;
}();

// nan_to_num(nan=0, posinf=100, neginf=-100)
__device__ __forceinline__ float san(float v) {
    if (isnan(v)) return 0.f;
    if (isinf(v)) return v > 0.f ? 100.f : -100.f;
    return v;
}

__device__ __forceinline__ unsigned h2u(__half2 h) { return *(unsigned*)&h; }

__device__ __forceinline__ float4 ldh4(const __half* p) {
    uint2 w = *(const uint2*)p;
    float2 a = __half22float2(*(__half2*)&w.x);
    float2 b = __half22float2(*(__half2*)&w.y);
    return make_float4(a.x, a.y, b.x, b.y);
}
__device__ __forceinline__ float2 ldh2(const __half* p) {
    return __half22float2(*(const __half2*)p);
}

// m16n8k16 f16xf16 -> f32 accumulate
__device__ __forceinline__ void mma16816(float* c, const unsigned* a, unsigned b0, unsigned b1) {
    asm volatile(
        "mma.sync.aligned.m16n8k16.row.col.f32.f16.f16.f32 "
        "{%0,%1,%2,%3}, {%4,%5,%6,%7}, {%8,%9}, {%0,%1,%2,%3};"
        : "+f"(c[0]), "+f"(c[1]), "+f"(c[2]), "+f"(c[3])
        : "r"(a[0]), "r"(a[1]), "r"(a[2]), "r"(a[3]), "r"(b0), "r"(b1));
}

// ---------------- single-pass bucketed CSR fill ----------------
__global__ void fill_kernel(const int* __restrict__ ei, int* __restrict__ cnt,
                            int* __restrict__ bkt, int E) {
    int e = blockIdx.x * blockDim.x + threadIdx.x;
    if (e < E) {
        int c = ei[E + e];
        int pos = atomicAdd(&cnt[c], 1);
        bkt[(unsigned)c * BCAP + pos] = ei[e];
    }
}

// dinv[i] = rsqrt(cnt[i]); block 0 also zeroes ALL 392 BN-stats words (strided)
__global__ void dinv_kernel(const int* __restrict__ cnt, float* __restrict__ dinv,
                            float* __restrict__ stats, int n) {
    int i = blockIdx.x * blockDim.x + threadIdx.x;
    if (blockIdx.x == 0) {
        for (int j = threadIdx.x; j < 392; j += 256) stats[j] = 0.f;
    }
    if (i < n) {
        int d = cnt[i];
        dinv[i] = d > 0 ? rsqrtf((float)d) : 0.f;
    }
}

// ---------------- in-place row scale of m0: m[row,:] *= dinv[row] (F=64, fp16) ----------
__global__ void scale_m_kernel(__half* __restrict__ m, const float* __restrict__ dinv, int n) {
    int i = blockIdx.x * blockDim.x + threadIdx.x;  // one thread per 8 halves
    int total = n * 8;
    if (i < total) {
        int row = i >> 3;
        float sc = dinv[row];
        uint4 w = *(uint4*)(m + (size_t)i * 8);
        __half2* h = (__half2*)&w;
        #pragma unroll
        for (int k = 0; k < 4; k++) {
            float2 f = __half22float2(h[k]);
            h[k] = __floats2half2_rn(f.x * sc, f.y * sc);
        }
        *(uint4*)(m + (size_t)i * 8) = w;
    }
}

// ================= HMMA GEMM (layer 0): C[128,64] = A[*,64] @ B[64,64], fp16 out ======
__global__ __launch_bounds__(256) void hgemm0_kernel(const float* __restrict__ A,
                                                     const float* __restrict__ B,
                                                     __half* __restrict__ C, int n) {
    constexpr int ASTR = 72;
    constexpr int BSTR = 72;
    __shared__ __half  As[128 * ASTR];
    __shared__ unsigned Bs[32 * BSTR];

    int tid = threadIdx.x;
    int row0 = blockIdx.x * 128;

    #pragma unroll
    for (int i = 0; i < 16; i++) {
        int idx = tid + 256 * i;
        int r = idx >> 5, kp = idx & 31;
        float v0 = 0.f, v1 = 0.f;
        if (row0 + r < n) {
            unsigned o = (unsigned)(row0 + r) * 64u + kp * 2;
            float2 av = *(const float2*)&A[o];
            v0 = av.x; v1 = av.y;
        }
        *(unsigned*)&As[r * ASTR + kp * 2] = h2u(__floats2half2_rn(v0, v1));
    }
    #pragma unroll
    for (int i = 0; i < 8; i++) {
        int idx = tid + 256 * i;
        int kp = idx >> 6, nn = idx & 63;
        Bs[kp * BSTR + nn] = h2u(__floats2half2_rn(B[(2 * kp) * 64 + nn],
                                                   B[(2 * kp + 1) * 64 + nn]));
    }
    __syncthreads();

    int warp = tid >> 5, lane = tid & 31;
    int wr = warp >> 1, wc = warp & 1;
    int rbase = wr * 32, nbase = wc * 32;
    int g = lane >> 2, q = lane & 3;

    float acc[2][4][4];
    #pragma unroll
    for (int mt = 0; mt < 2; mt++)
        #pragma unroll
        for (int nt = 0; nt < 4; nt++)
            #pragma unroll
            for (int e = 0; e < 4; e++) acc[mt][nt][e] = 0.f;

    #pragma unroll
    for (int kk = 0; kk < 4; kk++) {
        unsigned a[2][4];
        #pragma unroll
        for (int mt = 0; mt < 2; mt++) {
            const __half* ap = &As[(rbase + mt * 16 + g) * ASTR + kk * 16 + q * 2];
            a[mt][0] = *(const unsigned*)ap;
            a[mt][1] = *(const unsigned*)(ap + 8 * ASTR);
            a[mt][2] = *(const unsigned*)(ap + 8);
            a[mt][3] = *(const unsigned*)(ap + 8 * ASTR + 8);
        }
        int kp = kk * 8 + q;
        #pragma unroll
        for (int nt = 0; nt < 4; nt++) {
            int nn = nbase + nt * 8 + g;
            unsigned b0 = Bs[kp * BSTR + nn];
            unsigned b1 = Bs[(kp + 4) * BSTR + nn];
            mma16816(acc[0][nt], a[0], b0, b1);
            mma16816(acc[1][nt], a[1], b0, b1);
        }
    }

    #pragma unroll
    for (int mt = 0; mt < 2; mt++) {
        #pragma unroll
        for (int h = 0; h < 2; h++) {
            int r = row0 + rbase + mt * 16 + g + h * 8;
            if (r < n) {
                #pragma unroll
                for (int nt = 0; nt < 4; nt++) {
                    float c0 = acc[mt][nt][h * 2], c1 = acc[mt][nt][h * 2 + 1];
                    int col = nbase + nt * 8 + q * 2;
                    *(unsigned*)&C[(unsigned)r * 64 + col] = h2u(__floats2half2_rn(c0, c1));
                }
            }
        }
    }
}

// ====== merged layer-1 GEMM: one A pass -> m1 (fp16*dinv) + proj (fp32); inline BN0 ======
__global__ __launch_bounds__(256) void hgemm1m_kernel(const float* __restrict__ agg0,
                                                      const float* __restrict__ x,
                                                      const float* __restrict__ stats,
                                                      const float* __restrict__ gam,
                                                      const float* __restrict__ bet,
                                                      const float* __restrict__ W1,
                                                      const float* __restrict__ R1,
                                                      const float* __restrict__ dinv,
                                                      __half* __restrict__ mOut,
                                                      float* __restrict__ projOut, int n) {
    constexpr int ASTR = 72;
    constexpr int BSTR = 264;
    __shared__ __half  As[64 * ASTR];
    __shared__ unsigned Bs[32 * BSTR];
    __shared__ float sab[128];

    int tid = threadIdx.x;
    int row0 = blockIdx.x * 64;

    if (tid < 64) {
        int c = tid;
        float inv_n = 1.f / (float)n;
        float mu = stats[c] * inv_n;
        float var = fmaxf(stats[64 + c] * inv_n - mu * mu, 0.f);
        float a = gam[c] * rsqrtf(var + 1e-5f);
        sab[c] = a;
        sab[64 + c] = bet[c] - a * mu;
    }
    __syncthreads();

    #pragma unroll
    for (int i = 0; i < 8; i++) {
        int idx = tid + 256 * i;
        int r = idx >> 5, kp = idx & 31;
        float v0 = 0.f, v1 = 0.f;
        if (row0 + r < n) {
            unsigned o = (unsigned)(row0 + r) * 64u + kp * 2;
            float2 av = *(const float2*)&agg0[o];
            float2 xv = *(const float2*)&x[o];
            float t0 = fmaf(sab[kp * 2], av.x, sab[64 + kp * 2]);
            float t1 = fmaf(sab[kp * 2 + 1], av.y, sab[64 + kp * 2 + 1]);
            v0 = san(fmaxf(t0, 0.f) + xv.x);
            v1 = san(fmaxf(t1, 0.f) + xv.y);
        }
        *(unsigned*)&As[r * ASTR + kp * 2] = h2u(__floats2half2_rn(v0, v1));
    }
    #pragma unroll
    for (int i = 0; i < 32; i++) {
        int idx = tid + 256 * i;
        int kp = idx >> 8, nn = idx & 255;
        float b0, b1;
        if (nn < 128) {
            b0 = W1[(2 * kp) * 128 + nn];
            b1 = W1[(2 * kp + 1) * 128 + nn];
        } else {
            b0 = R1[(2 * kp) * 128 + nn - 128];
            b1 = R1[(2 * kp + 1) * 128 + nn - 128];
        }
        Bs[kp * BSTR + nn] = h2u(__floats2half2_rn(b0, b1));
    }
    __syncthreads();

    int warp = tid >> 5, lane = tid & 31;
    int wr = warp >> 2, wc = warp & 3;
    int rbase = wr * 32, nbase = wc * 64;
    int g = lane >> 2, q = lane & 3;

    float acc[2][8][4];
    #pragma unroll
    for (int mt = 0; mt < 2; mt++)
        #pragma unroll
        for (int nt = 0; nt < 8; nt++)
            #pragma unroll
            for (int e = 0; e < 4; e++) acc[mt][nt][e] = 0.f;

    #pragma unroll
    for (int kk = 0; kk < 4; kk++) {
        unsigned a[2][4];
        #pragma unroll
        for (int mt = 0; mt < 2; mt++) {
            const __half* ap = &As[(rbase + mt * 16 + g) * ASTR + kk * 16 + q * 2];
            a[mt][0] = *(const unsigned*)ap;
            a[mt][1] = *(const unsigned*)(ap + 8 * ASTR);
            a[mt][2] = *(const unsigned*)(ap + 8);
            a[mt][3] = *(const unsigned*)(ap + 8 * ASTR + 8);
        }
        int kp = kk * 8 + q;
        #pragma unroll
        for (int nt = 0; nt < 8; nt++) {
            int nn = nbase + nt * 8 + g;
            unsigned b0 = Bs[kp * BSTR + nn];
            unsigned b1 = Bs[(kp + 4) * BSTR + nn];
            mma16816(acc[0][nt], a[0], b0, b1);
            mma16816(acc[1][nt], a[1], b0, b1);
        }
    }

    bool isM = (nbase < 128);
    #pragma unroll
    for (int mt = 0; mt < 2; mt++) {
        #pragma unroll
        for (int h = 0; h < 2; h++) {
            int r = row0 + rbase + mt * 16 + g + h * 8;
            if (r < n) {
                if (isM) {
                    float sc = dinv[r];
                    #pragma unroll
                    for (int nt = 0; nt < 8; nt++) {
                        float c0 = acc[mt][nt][h * 2] * sc, c1 = acc[mt][nt][h * 2 + 1] * sc;
                        int col = nbase + nt * 8 + q * 2;
                        *(unsigned*)&mOut[(unsigned)r * 128 + col] = h2u(__floats2half2_rn(c0, c1));
                    }
                } else {
                    #pragma unroll
                    for (int nt = 0; nt < 8; nt++) {
                        float c0 = acc[mt][nt][h * 2], c1 = acc[mt][nt][h * 2 + 1];
                        int col = nbase + nt * 8 + q * 2 - 128;
                        *(float2*)&projOut[(unsigned)r * 128 + col] = make_float2(c0, c1);
                    }
                }
            }
        }
    }
}

// ===== gather layer 0 (add-only, m pre-scaled by dinv[row]) + fused BN stats =====
__global__ __launch_bounds__(256) void gather64_kernel(const int* __restrict__ cnt,
                                                       const int* __restrict__ bkt,
                                                       const float* __restrict__ dinv,
                                                       const __half* __restrict__ m,
                                                       float* __restrict__ agg,
                                                       float* __restrict__ stats, int n) {
    __shared__ float ssum[64], ssq[64];
    if (threadIdx.x < 64) { ssum[threadIdx.x] = 0.f; ssq[threadIdx.x] = 0.f; }
    __syncthreads();

    int node = (blockIdx.x * blockDim.x + threadIdx.x) >> 5;
    int lane = threadIdx.x & 31;
    float a0 = 0.f, a1 = 0.f;
    float o0 = 0.f, o1 = 0.f;

    if (node < n) {
        int cn = cnt[node];
        unsigned base = (unsigned)node * BCAP;
        float dc = dinv[node];
        for (int i = 0; i < cn; i += 32) {
            int idx = i + lane;
            int r = (idx < cn) ? bkt[base + idx] : 0;
            int c2 = min(32, cn - i);
            int j = 0;
            for (; j + 8 <= c2; j += 8) {
                unsigned rr[8];
                #pragma unroll
                for (int t = 0; t < 8; t++)
                    rr[t] = (unsigned)__shfl_sync(0xffffffffu, r, j + t);
                float2 v[8];
                #pragma unroll
                for (int t = 0; t < 8; t++) v[t] = ldh2(m + rr[t] * 64 + lane * 2);
                #pragma unroll
                for (int t = 0; t < 8; t++) {
                    a0 += v[t].x;
                    a1 += v[t].y;
                }
            }
            for (; j < c2; j++) {
                unsigned rr = (unsigned)__shfl_sync(0xffffffffu, r, j);
                float2 v = ldh2(m + rr * 64 + lane * 2);
                a0 += v.x;
                a1 += v.y;
            }
        }
        o0 = a0 * dc; o1 = a1 * dc;
        *(float2*)&agg[(unsigned)node * 64 + lane * 2] = make_float2(o0, o1);
    }

    atomicAdd(&ssum[lane * 2], o0);
    atomicAdd(&ssum[lane * 2 + 1], o1);
    atomicAdd(&ssq[lane * 2], o0 * o0);
    atomicAdd(&ssq[lane * 2 + 1], o1 * o1);
    __syncthreads();
    if (threadIdx.x < 64) {
        atomicAdd(&stats[threadIdx.x], ssum[threadIdx.x]);
        atomicAdd(&stats[64 + threadIdx.x], ssq[threadIdx.x]);
    }
}

// ===== gather layer 1 (exact R13 form, 8-deep, m pre-scaled) + fused BN stats =====
__global__ __launch_bounds__(256) void gather128_kernel(const int* __restrict__ cnt,
                                                        const int* __restrict__ bkt,
                                                        const float* __restrict__ dinv,
                                                        const __half* __restrict__ m,
                                                        float* __restrict__ agg,
                                                        float* __restrict__ stats, int n) {
    __shared__ float ssum[128], ssq[128];
    if (threadIdx.x < 128) { ssum[threadIdx.x] = 0.f; ssq[threadIdx.x] = 0.f; }
    __syncthreads();

    int node = (blockIdx.x * blockDim.x + threadIdx.x) >> 5;
    int lane = threadIdx.x & 31;
    float acc[4] = {0.f, 0.f, 0.f, 0.f};
    float out[4] = {0.f, 0.f, 0.f, 0.f};

    if (node < n) {
        int cn = cnt[node];
        unsigned base = (unsigned)node * BCAP;
        float dc = dinv[node];
        for (int i = 0; i < cn; i += 32) {
            int idx = i + lane;
            int r = (idx < cn) ? bkt[base + idx] : 0;
            int c2 = min(32, cn - i);
            int j = 0;
            for (; j + 8 <= c2; j += 8) {
                unsigned rr[8];
                #pragma unroll
                for (int t = 0; t < 8; t++)
                    rr[t] = (unsigned)__shfl_sync(0xffffffffu, r, j + t);
                float4 v[8];
                #pragma unroll
                for (int t = 0; t < 8; t++) v[t] = ldh4(m + rr[t] * 128 + lane * 4);
                #pragma unroll
                for (int t = 0; t < 8; t++) {
                    acc[0] += v[t].x; acc[1] += v[t].y;
                    acc[2] += v[t].z; acc[3] += v[t].w;
                }
            }
            for (; j < c2; j++) {
                unsigned rr = (unsigned)__shfl_sync(0xffffffffu, r, j);
                float4 v = ldh4(m + rr * 128 + lane * 4);
                acc[0] += v.x; acc[1] += v.y; acc[2] += v.z; acc[3] += v.w;
            }
        }
        #pragma unroll
        for (int v = 0; v < 4; v++) out[v] = acc[v] * dc;
        *(float4*)&agg[(unsigned)node * 128 + lane * 4] = make_float4(out[0], out[1], out[2], out[3]);
    }

    #pragma unroll
    for (int v = 0; v < 4; v++) {
        int c = lane * 4 + v;
        atomicAdd(&ssum[c], out[v]);
        atomicAdd(&ssq[c], out[v] * out[v]);
    }
    __syncthreads();
    if (threadIdx.x < 128) {
        atomicAdd(&stats[threadIdx.x], ssum[threadIdx.x]);
        atomicAdd(&stats[128 + threadIdx.x], ssq[threadIdx.x]);
    }
}

// ====== head: fc1+fc2+softmax with inline BN1 finalize for both slices ======
__global__ __launch_bounds__(256) void head_kernel(const float* __restrict__ B,
                                                   const float* __restrict__ bias,
                                                   const float* __restrict__ gam,
                                                   const float* __restrict__ bet,
                                                   const float* __restrict__ W2,
                                                   const float* __restrict__ b2,
                                                   float* __restrict__ out, int n) {
    constexpr int ASTR = 72;
    constexpr int BSTR = 136;
    __shared__ __half  As[128 * ASTR];
    __shared__ unsigned Bs[32 * BSTR];
    __shared__ float slog[256];
    __shared__ float sab[2][256];

    int tid = threadIdx.x;
    int row0 = blockIdx.x * 128;
    int warp = tid >> 5, lane = tid & 31;
    int wr = warp >> 1, wc = warp & 1;
    int rbase = wr * 32, nbase = wc * 64;
    int g = lane >> 2, q = lane & 3;

    slog[tid] = 0.f;
    {
        int s = tid >> 7, c = tid & 127;
        const float* st = &g_stats[s][128];
        float inv_n = 1.f / (float)n;
        float mu = st[c] * inv_n;
        float var = fmaxf(st[128 + c] * inv_n - mu * mu, 0.f);
        float a = gam[c] * rsqrtf(var + 1e-5f);
        sab[s][c] = a;
        sab[s][128 + c] = bet[c] - a * mu;
    }

    float acc[2][8][4];
    #pragma unroll
    for (int mt = 0; mt < 2; mt++)
        #pragma unroll
        for (int nt = 0; nt < 8; nt++)
            #pragma unroll
            for (int e = 0; e < 4; e++) acc[mt][nt][e] = 0.f;

    for (int c = 0; c < 4; c++) {
        __syncthreads();
        int s = c >> 1;
        const float* agg = g_agg1[s];
        const float* prj = g_proj[s];
        const float* ab  = sab[s];
        int kbase = (c & 1) * 64;
        #pragma unroll
        for (int i = 0; i < 16; i++) {
            int idx = tid + 256 * i;
            int r = idx >> 5, kp = idx & 31;
            float v0 = 0.f, v1 = 0.f;
            if (row0 + r < n) {
                int ch = kbase + kp * 2;
                unsigned o = (unsigned)(row0 + r) * 128u + ch;
                float2 av = *(const float2*)&agg[o];
                float2 pv = *(const float2*)&prj[o];
                v0 = san(fmaf(ab[ch], av.x, ab[128 + ch]) + pv.x);
                v1 = san(fmaf(ab[ch + 1], av.y, ab[128 + ch + 1]) + pv.y);
            }
            *(unsigned*)&As[r * ASTR + kp * 2] = h2u(__floats2half2_rn(v0, v1));
        }
        const float* Bc = B + c * 64 * 128;
        #pragma unroll
        for (int i = 0; i < 16; i++) {
            int idx = tid + 256 * i;
            int kp = idx >> 7, nn = idx & 127;
            Bs[kp * BSTR + nn] = h2u(__floats2half2_rn(Bc[(2 * kp) * 128 + nn],
                                                       Bc[(2 * kp + 1) * 128 + nn]));
        }
        __syncthreads();

        #pragma unroll
        for (int kk = 0; kk < 4; kk++) {
            unsigned a[2][4];
            #pragma unroll
            for (int mt = 0; mt < 2; mt++) {
                const __half* ap = &As[(rbase + mt * 16 + g) * ASTR + kk * 16 + q * 2];
                a[mt][0] = *(const unsigned*)ap;
                a[mt][1] = *(const unsigned*)(ap + 8 * ASTR);
                a[mt][2] = *(const unsigned*)(ap + 8);
                a[mt][3] = *(const unsigned*)(ap + 8 * ASTR + 8);
            }
            int kp = kk * 8 + q;
            #pragma unroll
            for (int nt = 0; nt < 8; nt++) {
                int nn = nbase + nt * 8 + g;
                unsigned b0 = Bs[kp * BSTR + nn];
                unsigned b1 = Bs[(kp + 4) * BSTR + nn];
                mma16816(acc[0][nt], a[0], b0, b1);
                mma16816(acc[1][nt], a[1], b0, b1);
            }
        }
    }
    __syncthreads();

    #pragma unroll
    for (int mt = 0; mt < 2; mt++) {
        #pragma unroll
        for (int h = 0; h < 2; h++) {
            int rl = rbase + mt * 16 + g + h * 8;
            float l0 = 0.f, l1 = 0.f;
            #pragma unroll
            for (int nt = 0; nt < 8; nt++) {
                int col = nbase + nt * 8 + q * 2;
                float h0 = fmaxf(acc[mt][nt][h * 2] + bias[col], 0.f);
                float h1 = fmaxf(acc[mt][nt][h * 2 + 1] + bias[col + 1], 0.f);
                l0 = fmaf(h0, W2[col * 2],     fmaf(h1, W2[(col + 1) * 2],     l0));
                l1 = fmaf(h0, W2[col * 2 + 1], fmaf(h1, W2[(col + 1) * 2 + 1], l1));
            }
            atomicAdd(&slog[rl * 2],     l0);
            atomicAdd(&slog[rl * 2 + 1], l1);
        }
    }
    __syncthreads();

    if (tid < 128) {
        int r = row0 + tid;
        if (r < n) {
            float l0 = slog[tid * 2] + b2[0];
            float l1 = slog[tid * 2 + 1] + b2[1];
            float mx = fmaxf(l0, l1);
            float e0 = expf(l0 - mx), e1 = expf(l1 - mx);
            float inv = 1.f / (e0 + e1);
            *(float2*)&out[(size_t)r * 2] = make_float2(l0, l1);
            *(float2*)&out[(size_t)2 * n + r * 2] = make_float2(e0 * inv, e1 * inv);
        }
    }
}

// ---------------- host launch (two streams per slice, graph-capturable) ----------------
extern "C" void kernel_launch(void* const* d_in, const int* in_sizes, int n_in,
                              void* d_out, int out_size) {
    const float* x     = (const float*)d_in[0];
    const int*   ei[2] = {(const int*)d_in[1], (const int*)d_in[2]};
    const float* w0[2]   = {(const float*)d_in[3], (const float*)d_in[8]};
    const float* w1[2]   = {(const float*)d_in[5], (const float*)d_in[10]};
    const float* res1[2] = {(const float*)d_in[7], (const float*)d_in[12]};
    const float* bn_g0 = (const float*)d_in[13];
    const float* bn_b0 = (const float*)d_in[14];
    const float* bn_g1 = (const float*)d_in[15];
    const float* bn_b1 = (const float*)d_in[16];
    const float* fc1_w = (const float*)d_in[17];
    const float* fc1_b = (const float*)d_in[18];
    const float* fc2_w = (const float*)d_in[19];
    const float* fc2_b = (const float*)d_in[20];

    int n = in_sizes[0] / 64;
    int E = in_sizes[1] / 2;

    float *dinv_p[2], *agg0_p[2], *agg1_p[2], *proj_p[2], *stats_p[2];
    __half* m_p[2];
    int *cnt_p[2], *bkt_p[2];
    {
        char* base;
        cudaGetSymbolAddress((void**)&base, g_dinv);
        dinv_p[0] = (float*)base; dinv_p[1] = dinv_p[0] + MAXN;
        cudaGetSymbolAddress((void**)&base, g_cnt);
        cnt_p[0] = (int*)base; cnt_p[1] = cnt_p[0] + MAXN;
        cudaGetSymbolAddress((void**)&base, g_bkt);
        bkt_p[0] = (int*)base; bkt_p[1] = bkt_p[0] + (size_t)MAXN * BCAP;
        cudaGetSymbolAddress((void**)&base, g_m);
        m_p[0] = (__half*)base; m_p[1] = m_p[0] + (size_t)MAXN * 128;
        cudaGetSymbolAddress((void**)&base, g_agg0);
        agg0_p[0] = (float*)base; agg0_p[1] = agg0_p[0] + (size_t)MAXN * 64;
        cudaGetSymbolAddress((void**)&base, g_agg1);
        agg1_p[0] = (float*)base; agg1_p[1] = agg1_p[0] + (size_t)MAXN * 128;
        cudaGetSymbolAddress((void**)&base, g_proj);
        proj_p[0] = (float*)base; proj_p[1] = proj_p[0] + (size_t)MAXN * 128;
        cudaGetSymbolAddress((void**)&base, g_stats);
        stats_p[0] = (float*)base; stats_p[1] = stats_p[0] + 392;
    }

    int ebl  = (E + 255) / 256;
    int nbl  = (n + 255) / 256;
    int sbl  = (n * 8 + 255) / 256;  // scale_m threads: one per 8 halves
    int hbl  = (n + 127) / 128;      // 128-row gemm blocks
    int g1bl = (n + 63) / 64;        // merged layer-1 gemm blocks
    int wbl  = (n + 7) / 8;          // warp-per-node gathers

    cudaEventRecord(g_ev[0], 0);

    for (int s = 0; s < 2; s++) {
        cudaStream_t a = g_str[2 * s];
        cudaStream_t b = g_str[2 * s + 1];
        cudaEvent_t evG0   = g_ev[1 + 2 * s];
        cudaEvent_t evDone = g_ev[2 + 2 * s];

        cudaStreamWaitEvent(a, g_ev[0], 0);
        cudaStreamWaitEvent(b, g_ev[0], 0);

        // stream a: single-pass bucketed CSR, then dinv (+full stats zero)
        cudaMemsetAsync(cnt_p[s], 0, n * sizeof(int), a);
        fill_kernel<<<ebl, 256, 0, a>>>(ei[s], cnt_p[s], bkt_p[s], E);
        dinv_kernel<<<nbl, 256, 0, a>>>(cnt_p[s], dinv_p[s], stats_p[s], n);

        // stream b: layer-0 GEMM (unscaled fp16; zero dependencies -> starts at t=0)
        hgemm0_kernel<<<hbl, 256, 0, b>>>(x, w0[s], m_p[s], n);
        cudaEventRecord(evG0, b);

        // join: scale m0 rows by dinv (3us), then add-only gather64 + BN stats
        cudaStreamWaitEvent(a, evG0, 0);
        scale_m_kernel<<<sbl, 256, 0, a>>>(m_p[s], dinv_p[s], n);
        gather64_kernel<<<wbl, 256, 0, a>>>(cnt_p[s], bkt_p[s], dinv_p[s], m_p[s],
                                            agg0_p[s], stats_p[s], n);

        // merged layer-1 GEMM: m1 (fp16*dinv) + proj (fp32) in one pass (inline BN0)
        hgemm1m_kernel<<<g1bl, 256, 0, a>>>(agg0_p[s], x, stats_p[s], bn_g0, bn_b0,
                                            w1[s], res1[s], dinv_p[s],
                                            m_p[s], proj_p[s], n);

        // gather layer 1 (R13 form, pre-scaled m1 + fused BN stats)
        gather128_kernel<<<wbl, 256, 0, a>>>(cnt_p[s], bkt_p[s], dinv_p[s], m_p[s],
                                             agg1_p[s], stats_p[s] + 128, n);
        cudaEventRecord(evDone, a);
    }

    // join both slices back to origin stream; fused head (inline BN1 finalize)
    cudaStreamWaitEvent(0, g_ev[2], 0);
    cudaStreamWaitEvent(0, g_ev[4], 0);
    head_kernel<<<hbl, 256>>>(fc1_w, fc1_b, bn_g1, bn_b1, fc2_w, fc2_b, (float*)d_out, n);
}